// round 13
// baseline (speedup 1.0000x reference)
#include <cuda_runtime.h>
#include <cub/cub.cuh>
#include <cstdint>

#define B_    8
#define L_    1024
#define H_    768
#define E_    16
#define W_    504
#define DFF_  512
#define NSPAN 5982
#define NE_   (NSPAN*E_)        /* 95712 */
#define BNE_  (B_*NE_)          /* 765696 */
#define BNS_  (B_*NSPAN)        /* 47856 */
#define FULLM 0xffffffffu

// ---------------- scratch (device globals; no runtime allocation) ----------
__device__ float g_word_emb[B_*W_*H_];
__device__ int   g_cnt[B_*W_];
__device__ int   g_wlist[B_*W_*8];
__device__ int   g_entpos[B_*E_];
__device__ float g_h1[B_*E_*DFF_];
__device__ float g_entvec[B_*E_*H_];
__device__ float g_G[B_*E_*DFF_];               // span_w2 @ ent_vec^T
__device__ float g_c[B_*E_];                    // span_b2 . ent_vec
__device__ float g_Bpack[H_*2*DFF_];            // [768,1024] packed span_w1
__device__ float g_sw2t[H_*DFF_];               // span_w2 transposed [768,512]
__device__ float g_part[6*B_*E_*DFF_];          // split-K partials (reused 3x)
__device__ float g_PQ[B_*W_*2*DFF_];            // per word: P(512) | Q(512)
__device__ unsigned g_k32 [BNS_];               // per-span max: dsc key (32-bit)
__device__ unsigned g_k32o[BNS_];
__device__ unsigned g_v32 [BNS_];               // payload: n*16 + entity
__device__ unsigned g_v32o[BNS_];
__device__ const int g_soff[B_ + 1] = {0, 5982, 11964, 17946, 23928,
                                       29910, 35892, 41874, 47856};
__device__ __align__(256) unsigned char g_cub_temp[16u*1024u*1024u];

// span id -> (start, end), pure arithmetic
__device__ __forceinline__ void span_of(int n, int& s, int& e) {
    if (n < 5916) { s = n / 12; e = s + n % 12; }
    else {
        int r = n - 5916; s = 493;
        while (r >= W_ - s) { r -= W_ - s; s++; }
        e = s + r;
    }
}

// -------- setup0: zero counters + entity-position scan (stream 0) -----------
__global__ void k_setup0(const int* __restrict__ emask) {
    int i = blockIdx.x * blockDim.x + threadIdx.x;
    int stride = gridDim.x * blockDim.x;
    for (int t = i; t < B_*W_; t += stride) g_cnt[t] = 0;
    if (blockIdx.x == 0 && threadIdx.x < 256) {
        int warp = threadIdx.x >> 5, lane = threadIdx.x & 31;
        int b = warp, cnt = 0;
        for (int pass = 0; pass < 2 && cnt < E_; pass++) {
            for (int base = 0; base < L_ && cnt < E_; base += 32) {
                int m = emask[b*L_ + base + lane];
                unsigned bal = __ballot_sync(FULLM, pass == 0 ? (m == 1) : (m != 1));
                while (bal && cnt < E_) {
                    int j = __ffs(bal) - 1; bal &= bal - 1;
                    if (lane == 0) g_entpos[b*E_ + cnt] = base + j;
                    cnt++;
                }
            }
        }
    }
}

// -------- prep: pack span_w1 + transpose span_w2 (stream B) -----------------
__global__ void k_prep(const float* __restrict__ sw1, const float* __restrict__ sw2) {
    int i = blockIdx.x * blockDim.x + threadIdx.x;
    int stride = gridDim.x * blockDim.x;
    for (int t = i; t < H_*2*DFF_; t += stride) {
        int k = t >> 10, j = t & 1023;
        g_Bpack[t] = (j < DFF_) ? sw1[(size_t)k*DFF_ + j]
                                : sw1[(size_t)(H_ + k)*DFF_ + (j - DFF_)];
    }
    for (int t = i; t < H_*DFF_; t += stride) {
        int h = t / DFF_, c = t - h*DFF_;
        g_sw2t[t] = sw2[(size_t)c*H_ + h];
    }
}

__global__ void k_zerosel(float* __restrict__ sel) {
    int i = blockIdx.x * blockDim.x + threadIdx.x;
    if (i < BNE_) sel[i] = 0.f;
}

// ---------------- build per-word token lists --------------------------------
__global__ void k_build(const int* __restrict__ tmask, const int* __restrict__ widx) {
    int t = blockIdx.x * blockDim.x + threadIdx.x;
    if (t >= B_*L_) return;
    if (tmask[t] != 1) return;
    int w = widx[t];
    if (w < 0 || w >= W_) return;
    int b = t >> 10;
    int slot = atomicAdd(&g_cnt[b*W_ + w], 1);
    if (slot < 8) g_wlist[(b*W_ + w)*8 + slot] = t;
}

// ---------------- gather mean pooling: 1 warp per word ----------------------
__global__ void __launch_bounds__(256) k_pool2(const float* __restrict__ hs) {
    int word = blockIdx.x * 8 + (threadIdx.x >> 5);
    if (word >= B_*W_) return;
    int lane = threadIdx.x & 31;
    int cnt = g_cnt[word];
    int m = cnt < 8 ? cnt : 8;
    int tk[8];
#pragma unroll
    for (int i = 0; i < 8; i++) tk[i] = (i < m) ? g_wlist[word*8 + i] : 0x7fffffff;
#pragma unroll
    for (int p = 0; p < 8; p++)
#pragma unroll
        for (int i = 0; i < 7; i++)
            if (tk[i] > tk[i+1]) { int z = tk[i]; tk[i] = tk[i+1]; tk[i+1] = z; }
    float ax[6], ay[6], az[6], aw[6];
#pragma unroll
    for (int c = 0; c < 6; c++) { ax[c]=0.f; ay[c]=0.f; az[c]=0.f; aw[c]=0.f; }
#pragma unroll
    for (int j = 0; j < 8; j++) {
        if (tk[j] == 0x7fffffff) continue;
        const float4* src = (const float4*)&hs[(size_t)tk[j]*H_];
#pragma unroll
        for (int c = 0; c < 6; c++) {
            float4 v = src[lane + c*32];
            ax[c]+=v.x; ay[c]+=v.y; az[c]+=v.z; aw[c]+=v.w;
        }
    }
    float inv = 1.f / (float)(cnt > 1 ? cnt : 1);
    float4* dst = (float4*)&g_word_emb[(size_t)word*H_];
#pragma unroll
    for (int c = 0; c < 6; c++) {
        float4 v; v.x=ax[c]*inv; v.y=ay[c]*inv; v.z=az[c]*inv; v.w=aw[c]*inv;
        dst[lane + c*32] = v;
    }
}

// ---------------- GEMM: PQ[4032,1024] = word_emb[4032,768] @ Bpack ----------
__global__ void __launch_bounds__(256) k_gemm() {
    __shared__ float sA[2][16][68];
    __shared__ float sB[2][16][128];
    int bm = blockIdx.y * 64, bn = blockIdx.x * 128;
    int tid = threadIdx.x;
    int tx = tid & 15, ty = tid >> 4;
    int ar = tid >> 2, ak = (tid & 3) * 4;
    int bk = tid >> 5, bc = (tid & 31) * 4;
    const float* Ag  = &g_word_emb[(size_t)(bm + ar)*H_ + ak];
    const float* Bg0 = &g_Bpack[(size_t)bk*1024 + bn + bc];
    const float* Bg1 = &g_Bpack[(size_t)(bk+8)*1024 + bn + bc];

    float acc[4][8];
#pragma unroll
    for (int i = 0; i < 4; i++)
#pragma unroll
        for (int j = 0; j < 8; j++) acc[i][j] = 0.f;

    float4 a0 = *(const float4*)(Ag);
    float4 b0 = *(const float4*)(Bg0);
    float4 b1 = *(const float4*)(Bg1);
    int buf = 0;
    sA[0][ak+0][ar]=a0.x; sA[0][ak+1][ar]=a0.y; sA[0][ak+2][ar]=a0.z; sA[0][ak+3][ar]=a0.w;
    *(float4*)&sB[0][bk  ][bc] = b0;
    *(float4*)&sB[0][bk+8][bc] = b1;
    __syncthreads();

    for (int t = 0; t < 48; t++) {
        bool last = (t == 47);
        if (!last) {
            int k0 = (t + 1) * 16;
            a0 = *(const float4*)(Ag + k0);
            b0 = *(const float4*)(Bg0 + (size_t)k0*1024);
            b1 = *(const float4*)(Bg1 + (size_t)k0*1024);
        }
#pragma unroll
        for (int k = 0; k < 16; k++) {
            float4 av  = *(const float4*)&sA[buf][k][ty*4];
            float4 bv0 = *(const float4*)&sB[buf][k][tx*4];
            float4 bv1 = *(const float4*)&sB[buf][k][64 + tx*4];
            float a4[4] = {av.x, av.y, av.z, av.w};
            float b8[8] = {bv0.x,bv0.y,bv0.z,bv0.w,bv1.x,bv1.y,bv1.z,bv1.w};
#pragma unroll
            for (int i = 0; i < 4; i++)
#pragma unroll
                for (int j = 0; j < 8; j++)
                    acc[i][j] = fmaf(a4[i], b8[j], acc[i][j]);
        }
        if (!last) {
            int nb = buf ^ 1;
            sA[nb][ak+0][ar]=a0.x; sA[nb][ak+1][ar]=a0.y; sA[nb][ak+2][ar]=a0.z; sA[nb][ak+3][ar]=a0.w;
            *(float4*)&sB[nb][bk  ][bc] = b0;
            *(float4*)&sB[nb][bk+8][bc] = b1;
            __syncthreads();
            buf = nb;
        }
    }
#pragma unroll
    for (int i = 0; i < 4; i++) {
        int row = bm + ty*4 + i;
        float4 v0; v0.x=acc[i][0]; v0.y=acc[i][1]; v0.z=acc[i][2]; v0.w=acc[i][3];
        float4 v1; v1.x=acc[i][4]; v1.y=acc[i][5]; v1.z=acc[i][6]; v1.w=acc[i][7];
        *(float4*)&g_PQ[(size_t)row*1024 + bn + tx*4]      = v0;
        *(float4*)&g_PQ[(size_t)row*1024 + bn + 64 + tx*4] = v1;
    }
}

// ====== entity chain, split-K: phase-1 kernels + deterministic reducers =====
__global__ void __launch_bounds__(128) k_l1p1(const float* __restrict__ hs,
                                              const float* __restrict__ w1) {
    __shared__ float st[E_*128];
    int b = blockIdx.z, kc = blockIdx.y << 7;
    int c = (blockIdx.x << 7) + threadIdx.x;
    for (int i = threadIdx.x; i < E_*128; i += 128) {
        int e = i >> 7, kk = i & 127;
        st[i] = hs[((size_t)(b*L_ + g_entpos[b*E_ + e]))*H_ + kc + kk];
    }
    __syncthreads();
    float acc[E_];
#pragma unroll
    for (int r = 0; r < E_; r++) acc[r] = 0.f;
    for (int kk = 0; kk < 128; kk++) {
        float w = w1[(size_t)(kc + kk)*DFF_ + c];
#pragma unroll
        for (int r = 0; r < E_; r++) acc[r] = fmaf(st[(r<<7) + kk], w, acc[r]);
    }
#pragma unroll
    for (int r = 0; r < E_; r++)
        g_part[((size_t)blockIdx.y*B_*E_ + b*E_ + r)*DFF_ + c] = acc[r];
}

__global__ void k_l1red(const float* __restrict__ b1) {
    int be = blockIdx.x;
    for (int c = threadIdx.x; c < DFF_; c += 128) {
        float s = b1[c];
#pragma unroll
        for (int kc = 0; kc < 6; kc++)
            s += g_part[((size_t)kc*B_*E_ + be)*DFF_ + c];
        g_h1[(size_t)be*DFF_ + c] = s > 0.f ? s : 0.01f*s;
    }
}

__global__ void __launch_bounds__(128) k_l2p1(const float* __restrict__ w2) {
    __shared__ float st[E_*128];
    int b = blockIdx.z, kc = blockIdx.y << 7;
    int c = (blockIdx.x << 7) + threadIdx.x;
    for (int i = threadIdx.x; i < E_*128; i += 128) {
        int e = i >> 7, kk = i & 127;
        st[i] = g_h1[((size_t)b*E_ + e)*DFF_ + kc + kk];
    }
    __syncthreads();
    float acc[E_];
#pragma unroll
    for (int r = 0; r < E_; r++) acc[r] = 0.f;
    for (int kk = 0; kk < 128; kk++) {
        float w = w2[(size_t)(kc + kk)*H_ + c];
#pragma unroll
        for (int r = 0; r < E_; r++) acc[r] = fmaf(st[(r<<7) + kk], w, acc[r]);
    }
#pragma unroll
    for (int r = 0; r < E_; r++)
        g_part[((size_t)blockIdx.y*B_*E_ + b*E_ + r)*H_ + c] = acc[r];
}

__global__ void k_l2red(const float* __restrict__ b2, const float* __restrict__ sb2) {
    __shared__ float red[256];
    int be = blockIdx.x;
    float dot = 0.f;
    for (int c = threadIdx.x; c < H_; c += 256) {
        float s = b2[c];
#pragma unroll
        for (int kc = 0; kc < 4; kc++)
            s += g_part[((size_t)kc*B_*E_ + be)*H_ + c];
        g_entvec[(size_t)be*H_ + c] = s;
        dot = fmaf(s, sb2[c], dot);
    }
    red[threadIdx.x] = dot;
    __syncthreads();
    if (threadIdx.x < 128) red[threadIdx.x] += red[threadIdx.x + 128];
    __syncthreads();
    if (threadIdx.x < 64) red[threadIdx.x] += red[threadIdx.x + 64];
    __syncthreads();
    if (threadIdx.x < 32) {
        float v = red[threadIdx.x] + red[threadIdx.x + 32];
#pragma unroll
        for (int o = 16; o; o >>= 1) v += __shfl_xor_sync(FULLM, v, o);
        if (threadIdx.x == 0) g_c[be] = v;
    }
}

__global__ void __launch_bounds__(128) k_gmp1() {
    __shared__ float st[E_*128];
    int b = blockIdx.z, kc = blockIdx.y << 7;
    int c = (blockIdx.x << 7) + threadIdx.x;
    for (int i = threadIdx.x; i < E_*128; i += 128) {
        int e = i >> 7, kk = i & 127;
        st[i] = g_entvec[((size_t)b*E_ + e)*H_ + kc + kk];
    }
    __syncthreads();
    float acc[E_];
#pragma unroll
    for (int r = 0; r < E_; r++) acc[r] = 0.f;
    for (int kk = 0; kk < 128; kk++) {
        float w = g_sw2t[(size_t)(kc + kk)*DFF_ + c];
#pragma unroll
        for (int r = 0; r < E_; r++) acc[r] = fmaf(st[(r<<7) + kk], w, acc[r]);
    }
#pragma unroll
    for (int r = 0; r < E_; r++)
        g_part[((size_t)blockIdx.y*B_*E_ + b*E_ + r)*DFF_ + c] = acc[r];
}

__global__ void k_gmred() {
    int be = blockIdx.x;
    for (int c = threadIdx.x; c < DFF_; c += 128) {
        float s = 0.f;
#pragma unroll
        for (int kc = 0; kc < 6; kc++)
            s += g_part[((size_t)kc*B_*E_ + be)*DFF_ + c];
        g_G[(size_t)be*DFF_ + c] = s;
    }
}

// --- logits: 2 spans/warp; emits per-span MAX as 32-bit key + payload --------
__global__ void __launch_bounds__(256, 2) k_logits(const float* __restrict__ sb1,
                                                   float* __restrict__ out1) {
    __shared__ float sG[E_*DFF_];
    __shared__ float sb[DFF_];
    int b = blockIdx.y;
    for (int i = threadIdx.x; i < E_*DFF_; i += 256) sG[i] = g_G[(size_t)b*E_*DFF_ + i];
    for (int i = threadIdx.x; i < DFF_;    i += 256) sb[i] = sb1[i];
    __syncthreads();
    int warp = threadIdx.x >> 5, lane = threadIdx.x & 31;
    int n0 = blockIdx.x * 16 + warp * 2;
    if (n0 >= NSPAN) return;

    const float4* P4[2]; const float4* Q4[2]; int nn[2];
#pragma unroll
    for (int t = 0; t < 2; t++) {
        nn[t] = n0 + t;
        int n = nn[t] < NSPAN ? nn[t] : NSPAN - 1;
        int s, e; span_of(n, s, e);
        P4[t] = (const float4*)&g_PQ[(size_t)(b*W_ + s) * 1024];
        Q4[t] = (const float4*)&g_PQ[(size_t)(b*W_ + e) * 1024 + 512];
    }
    float acc[2][16];
#pragma unroll
    for (int t = 0; t < 2; t++)
#pragma unroll
        for (int e2 = 0; e2 < 16; e2++) acc[t][e2] = 0.f;

#pragma unroll
    for (int j = 0; j < 4; j++) {
        int kq = lane + j*32;
        float4 bb = ((const float4*)sb)[kq];
        float4 h[2];
#pragma unroll
        for (int t = 0; t < 2; t++) {
            float4 p = P4[t][kq], q = Q4[t][kq];
            float x0 = p.x+q.x+bb.x, x1 = p.y+q.y+bb.y;
            float x2 = p.z+q.z+bb.z, x3 = p.w+q.w+bb.w;
            h[t].x = x0 > 0.f ? x0 : 0.01f*x0;
            h[t].y = x1 > 0.f ? x1 : 0.01f*x1;
            h[t].z = x2 > 0.f ? x2 : 0.01f*x2;
            h[t].w = x3 > 0.f ? x3 : 0.01f*x3;
        }
#pragma unroll
        for (int e2 = 0; e2 < 16; e2++) {
            float4 g = ((const float4*)sG)[e2*128 + kq];
#pragma unroll
            for (int t = 0; t < 2; t++)
                acc[t][e2] = fmaf(h[t].x, g.x, fmaf(h[t].y, g.y,
                             fmaf(h[t].z, g.z, fmaf(h[t].w, g.w, acc[t][e2]))));
        }
    }
    int e2out = (lane >> 1) & 15;
#pragma unroll
    for (int t = 0; t < 2; t++) {
        float* v = acc[t];
#pragma unroll
        for (int d = 16; d > 1; d >>= 1) {
            int half = d >> 1;
#pragma unroll
            for (int i = 0; i < 8; i++) {
                if (i >= half) break;
                float give = (lane & d) ? v[i] : v[i + half];
                float got  = __shfl_xor_sync(FULLM, give, d);
                float keep = (lane & d) ? v[i + half] : v[i];
                v[i] = keep + got;
            }
        }
        v[0] += __shfl_xor_sync(FULLM, v[0], 1);
        bool valid = nn[t] < NSPAN;
        float lg = v[0] + g_c[b*E_ + e2out];
        if (!(lane & 1) && valid)
            out1[((size_t)b*NSPAN + nn[t])*E_ + e2out] = lg;
        float mv = (!(lane & 1)) ? lg : __int_as_float(0xff800000);
        int   mi = (!(lane & 1)) ? e2out : 9999;
#pragma unroll
        for (int o = 1; o < 32; o <<= 1) {
            float ov = __shfl_xor_sync(FULLM, mv, o);
            int   oi = __shfl_xor_sync(FULLM, mi, o);
            if (ov > mv || (ov == mv && oi < mi)) { mv = ov; mi = oi; }
        }
        if (lane == 0 && valid) {
            unsigned u = __float_as_uint(mv);
            unsigned asc = (u & 0x80000000u) ? ~u : (u | 0x80000000u);
            g_k32[(size_t)b*NSPAN + nn[t]] = ~asc;   // ascending sort = logit desc
            g_v32[(size_t)b*NSPAN + nn[t]] = (unsigned)(nn[t]*E_ + mi);
        }
    }
}

// ------- greedy NMS decode over sorted per-span maxima: 1 block/batch -------
__global__ void __launch_bounds__(256) k_decode(float* __restrict__ sel) {
    int b = blockIdx.x;
    int tid = threadIdx.x, lane = tid & 31, warp = tid >> 5;
    __shared__ unsigned long long cov[8];
    __shared__ unsigned kt[512];
    __shared__ unsigned vt[512];
    __shared__ int done;
    if (tid < 8) cov[tid] = 0ULL;
    if (tid == 0) done = 0;
    __syncthreads();
    const unsigned* keys = g_k32o + (size_t)b*NSPAN;
    const unsigned* vals = g_v32o + (size_t)b*NSPAN;
    for (int t0 = 0; t0 < NSPAN; t0 += 512) {
        int i0 = t0 + tid;
        kt[tid]       = (i0       < NSPAN) ? keys[i0]       : 0xffffffffu;
        kt[tid + 256] = (i0 + 256 < NSPAN) ? keys[i0 + 256] : 0xffffffffu;
        vt[tid]       = (i0       < NSPAN) ? vals[i0]       : 0u;
        vt[tid + 256] = (i0 + 256 < NSPAN) ? vals[i0 + 256] : 0u;
        __syncthreads();
        if (warp == 0) {
            int stop = 0;
            for (int w0 = 0; w0 < 512; w0 += 32) {
                unsigned dsc = kt[w0 + lane];
                unsigned asc = ~dsc;
                bool pos = asc > 0x80000000u;        // logit > 0 <=> prob > 0.5
                unsigned pb = __ballot_sync(FULLM, pos);
                if (pb == 0u) { stop = 1; break; }
                int idx = (int)vt[w0 + lane];
                int n = idx >> 4;
                int s, e; span_of(n, s, e);
                int wd = s >> 6, off = s & 63, len = e - s + 1;
                unsigned long long bits = (1ULL << len) - 1ULL;
                unsigned long long m0 = bits << off;
                unsigned long long m1 = (off + len > 64) ? (bits >> (64 - off)) : 0ULL;
                unsigned long long c0 = cov[wd];
                unsigned long long c1 = (wd + 1 < 8) ? cov[wd+1] : 0ULL;
                bool alive = pos && !((c0 & m0) | (c1 & m1));
                unsigned ball = __ballot_sync(FULLM, alive);
                while (ball) {
                    int leader = __ffs(ball) - 1;
                    int lw = __shfl_sync(FULLM, wd, leader);
                    unsigned long long lm0 = __shfl_sync(FULLM, m0, leader);
                    unsigned long long lm1 = __shfl_sync(FULLM, m1, leader);
                    int lidx = __shfl_sync(FULLM, idx, leader);
                    if (lane == leader) {
                        cov[lw] |= lm0;
                        if (lw + 1 < 8) cov[lw+1] |= lm1;
                        sel[(size_t)b*NE_ + lidx] = 1.0f;
                        alive = false;
                    } else if (alive && lane > leader) {
                        unsigned long long o = 0ULL;
                        if      (lw == wd)     o = (lm0 & m0) | (lm1 & m1);
                        else if (lw == wd - 1) o = lm1 & m0;
                        else if (lw == wd + 1) o = lm0 & m1;
                        if (o) alive = false;
                    }
                    ball = __ballot_sync(FULLM, alive);
                }
                __syncwarp();
                unsigned long long cw = (lane < 8) ? cov[lane] : 0ULL;
                int pc = __popcll(cw);
#pragma unroll
                for (int o = 16; o; o >>= 1) pc += __shfl_xor_sync(FULLM, pc, o);
                if (pc >= W_) { stop = 1; break; }
                if (pb != FULLM) { stop = 1; break; }
            }
            if (lane == 0 && stop) done = 1;
        }
        __syncthreads();
        if (done) break;
        __syncthreads();
    }
}

extern "C" void kernel_launch(void* const* d_in, const int* in_sizes, int n_in,
                              void* d_out, int out_size) {
    const float* hs   = (const float*)d_in[0];
    const float* ew1  = (const float*)d_in[1];
    const float* eb1  = (const float*)d_in[2];
    const float* ew2  = (const float*)d_in[3];
    const float* eb2  = (const float*)d_in[4];
    const float* sw1  = (const float*)d_in[5];
    const float* sb1  = (const float*)d_in[6];
    const float* sw2  = (const float*)d_in[7];
    const float* sb2  = (const float*)d_in[8];
    const int* tmask  = (const int*)d_in[9];
    const int* emask  = (const int*)d_in[10];
    const int* widx   = (const int*)d_in[11];
    float* out = (float*)d_out;
    int write_sel = (out_size >= 2*BNE_);
    float* sel = write_sel ? out + BNE_ : nullptr;

    // ONE extra stream + events (R11-proven allocation-safe configuration)
    cudaStream_t sB;
    cudaStreamCreateWithFlags(&sB, cudaStreamNonBlocking);
    cudaEvent_t e0, eA, eP, eC;
    cudaEventCreateWithFlags(&e0, cudaEventDisableTiming);
    cudaEventCreateWithFlags(&eA, cudaEventDisableTiming);
    cudaEventCreateWithFlags(&eP, cudaEventDisableTiming);
    cudaEventCreateWithFlags(&eC, cudaEventDisableTiming);

    // stream 0: setup0 -> build -> pool2 -> gemm -> logits -> sort -> decode
    k_setup0<<<64, 256>>>(emask);
    cudaEventRecord(e0, 0);
    cudaEventRecord(eA, 0);
    k_build<<<(B_*L_ + 255)/256, 256>>>(tmask, widx);

    // stream B: prep -> zerosel -> entity chain
    cudaStreamWaitEvent(sB, e0, 0);
    k_prep<<<512, 256, 0, sB>>>(sw1, sw2);
    cudaEventRecord(eP, sB);
    k_pool2<<<(B_*W_ + 7)/8, 256>>>(hs);               // stream 0, slot 3 (ncu)
    if (write_sel) k_zerosel<<<(BNE_ + 255)/256, 256, 0, sB>>>(sel);
    cudaStreamWaitEvent(sB, eA, 0);
    k_l1p1<<<dim3(4, 6, B_), 128, 0, sB>>>(hs, ew1);
    k_l1red<<<B_*E_, 128, 0, sB>>>(eb1);
    k_l2p1<<<dim3(6, 4, B_), 128, 0, sB>>>(ew2);
    k_l2red<<<B_*E_, 256, 0, sB>>>(eb2, sb2);
    k_gmp1<<<dim3(4, 6, B_), 128, 0, sB>>>();
    k_gmred<<<B_*E_, 128, 0, sB>>>();
    cudaEventRecord(eC, sB);

    // stream 0: gemm (needs Bpack), then logits (needs chain)
    cudaStreamWaitEvent(0, eP, 0);
    k_gemm<<<dim3(8, 63), 256>>>();
    cudaStreamWaitEvent(0, eC, 0);
    k_logits<<<dim3((NSPAN + 15)/16, B_), 256>>>(sb1, out);

    if (write_sel) {
        void *pk, *pko, *pv, *pvo, *ptmp, *poff;
        cudaGetSymbolAddress(&pk,   g_k32);
        cudaGetSymbolAddress(&pko,  g_k32o);
        cudaGetSymbolAddress(&pv,   g_v32);
        cudaGetSymbolAddress(&pvo,  g_v32o);
        cudaGetSymbolAddress(&ptmp, g_cub_temp);
        cudaGetSymbolAddress(&poff, (const void*)g_soff);
        const int* offs = (const int*)poff;
        size_t tb = 0;
        cub::DeviceSegmentedRadixSort::SortPairs(nullptr, tb,
            (const unsigned*)pk, (unsigned*)pko, (const unsigned*)pv, (unsigned*)pvo,
            BNS_, B_, offs, offs + 1, 0, 32);
        if (tb <= sizeof(g_cub_temp)) {
            cub::DeviceSegmentedRadixSort::SortPairs(ptmp, tb,
                (const unsigned*)pk, (unsigned*)pko, (const unsigned*)pv, (unsigned*)pvo,
                BNS_, B_, offs, offs + 1, 0, 32);
        }
        k_decode<<<B_, 256>>>(sel);
    }
}

// round 14
// speedup vs baseline: 1.0631x; 1.0631x over previous
#include <cuda_runtime.h>
#include <cub/cub.cuh>
#include <cstdint>

#define B_    8
#define L_    1024
#define H_    768
#define E_    16
#define W_    504
#define DFF_  512
#define NSPAN 5982
#define NE_   (NSPAN*E_)        /* 95712 */
#define BNE_  (B_*NE_)          /* 765696 */
#define BNS_  (B_*NSPAN)        /* 47856 */
#define HNS_  (4*NSPAN)         /* half: 23928 */
#define FULLM 0xffffffffu

// ---------------- scratch (device globals; no runtime allocation) ----------
__device__ float g_word_emb[B_*W_*H_];
__device__ int   g_cnt[B_*W_];
__device__ int   g_wlist[B_*W_*8];
__device__ int   g_entpos[B_*E_];
__device__ float g_h1[B_*E_*DFF_];
__device__ float g_entvec[B_*E_*H_];
__device__ float g_G[B_*E_*DFF_];               // span_w2 @ ent_vec^T
__device__ float g_c[B_*E_];                    // span_b2 . ent_vec
__device__ float g_Bpack[H_*2*DFF_];            // [768,1024] packed span_w1
__device__ float g_sw2t[H_*DFF_];               // span_w2 transposed [768,512]
__device__ float g_part[6*B_*E_*DFF_];          // split-K partials (reused 3x)
__device__ float g_PQ[B_*W_*2*DFF_];            // per word: P(512) | Q(512)
__device__ unsigned long long g_keys_in[BNS_];
__device__ unsigned long long g_keys_out[BNS_];
__device__ __align__(256) unsigned char g_cub_temp[16u*1024u*1024u]; // 2 x 8MB

// span id -> (start, end), pure arithmetic
__device__ __forceinline__ void span_of(int n, int& s, int& e) {
    if (n < 5916) { s = n / 12; e = s + n % 12; }
    else {
        int r = n - 5916; s = 493;
        while (r >= W_ - s) { r -= W_ - s; s++; }
        e = s + r;
    }
}

// -------- setup0: zero counters + entity-position scan (stream 0) -----------
__global__ void k_setup0(const int* __restrict__ emask) {
    int i = blockIdx.x * blockDim.x + threadIdx.x;
    int stride = gridDim.x * blockDim.x;
    for (int t = i; t < B_*W_; t += stride) g_cnt[t] = 0;
    if (blockIdx.x == 0 && threadIdx.x < 256) {
        int warp = threadIdx.x >> 5, lane = threadIdx.x & 31;
        int b = warp, cnt = 0;
        for (int pass = 0; pass < 2 && cnt < E_; pass++) {
            for (int base = 0; base < L_ && cnt < E_; base += 32) {
                int m = emask[b*L_ + base + lane];
                unsigned bal = __ballot_sync(FULLM, pass == 0 ? (m == 1) : (m != 1));
                while (bal && cnt < E_) {
                    int j = __ffs(bal) - 1; bal &= bal - 1;
                    if (lane == 0) g_entpos[b*E_ + cnt] = base + j;
                    cnt++;
                }
            }
        }
    }
}

// -------- prep: pack span_w1 + transpose span_w2 (stream B) -----------------
__global__ void k_prep(const float* __restrict__ sw1, const float* __restrict__ sw2) {
    int i = blockIdx.x * blockDim.x + threadIdx.x;
    int stride = gridDim.x * blockDim.x;
    for (int t = i; t < H_*2*DFF_; t += stride) {
        int k = t >> 10, j = t & 1023;
        g_Bpack[t] = (j < DFF_) ? sw1[(size_t)k*DFF_ + j]
                                : sw1[(size_t)(H_ + k)*DFF_ + (j - DFF_)];
    }
    for (int t = i; t < H_*DFF_; t += stride) {
        int h = t / DFF_, c = t - h*DFF_;
        g_sw2t[t] = sw2[(size_t)c*H_ + h];
    }
}

// ---------------- build per-word token lists --------------------------------
__global__ void k_build(const int* __restrict__ tmask, const int* __restrict__ widx) {
    int t = blockIdx.x * blockDim.x + threadIdx.x;
    if (t >= B_*L_) return;
    if (tmask[t] != 1) return;
    int w = widx[t];
    if (w < 0 || w >= W_) return;
    int b = t >> 10;
    int slot = atomicAdd(&g_cnt[b*W_ + w], 1);
    if (slot < 8) g_wlist[(b*W_ + w)*8 + slot] = t;
}

// ---------------- gather mean pooling: 1 warp per word ----------------------
__global__ void __launch_bounds__(256) k_pool2(const float* __restrict__ hs) {
    int word = blockIdx.x * 8 + (threadIdx.x >> 5);
    if (word >= B_*W_) return;
    int lane = threadIdx.x & 31;
    int cnt = g_cnt[word];
    int m = cnt < 8 ? cnt : 8;
    int tk[8];
#pragma unroll
    for (int i = 0; i < 8; i++) tk[i] = (i < m) ? g_wlist[word*8 + i] : 0x7fffffff;
#pragma unroll
    for (int p = 0; p < 8; p++)
#pragma unroll
        for (int i = 0; i < 7; i++)
            if (tk[i] > tk[i+1]) { int z = tk[i]; tk[i] = tk[i+1]; tk[i+1] = z; }
    float ax[6], ay[6], az[6], aw[6];
#pragma unroll
    for (int c = 0; c < 6; c++) { ax[c]=0.f; ay[c]=0.f; az[c]=0.f; aw[c]=0.f; }
#pragma unroll
    for (int j = 0; j < 8; j++) {
        if (tk[j] == 0x7fffffff) continue;
        const float4* src = (const float4*)&hs[(size_t)tk[j]*H_];
#pragma unroll
        for (int c = 0; c < 6; c++) {
            float4 v = src[lane + c*32];
            ax[c]+=v.x; ay[c]+=v.y; az[c]+=v.z; aw[c]+=v.w;
        }
    }
    float inv = 1.f / (float)(cnt > 1 ? cnt : 1);
    float4* dst = (float4*)&g_word_emb[(size_t)word*H_];
#pragma unroll
    for (int c = 0; c < 6; c++) {
        float4 v; v.x=ax[c]*inv; v.y=ay[c]*inv; v.z=az[c]*inv; v.w=aw[c]*inv;
        dst[lane + c*32] = v;
    }
}

// ---------------- GEMM: PQ[4032,1024] = word_emb[4032,768] @ Bpack ----------
__global__ void __launch_bounds__(256) k_gemm() {
    __shared__ float sA[2][16][68];
    __shared__ float sB[2][16][128];
    int bm = blockIdx.y * 64, bn = blockIdx.x * 128;
    int tid = threadIdx.x;
    int tx = tid & 15, ty = tid >> 4;
    int ar = tid >> 2, ak = (tid & 3) * 4;
    int bk = tid >> 5, bc = (tid & 31) * 4;
    const float* Ag  = &g_word_emb[(size_t)(bm + ar)*H_ + ak];
    const float* Bg0 = &g_Bpack[(size_t)bk*1024 + bn + bc];
    const float* Bg1 = &g_Bpack[(size_t)(bk+8)*1024 + bn + bc];

    float acc[4][8];
#pragma unroll
    for (int i = 0; i < 4; i++)
#pragma unroll
        for (int j = 0; j < 8; j++) acc[i][j] = 0.f;

    float4 a0 = *(const float4*)(Ag);
    float4 b0 = *(const float4*)(Bg0);
    float4 b1 = *(const float4*)(Bg1);
    int buf = 0;
    sA[0][ak+0][ar]=a0.x; sA[0][ak+1][ar]=a0.y; sA[0][ak+2][ar]=a0.z; sA[0][ak+3][ar]=a0.w;
    *(float4*)&sB[0][bk  ][bc] = b0;
    *(float4*)&sB[0][bk+8][bc] = b1;
    __syncthreads();

    for (int t = 0; t < 48; t++) {
        bool last = (t == 47);
        if (!last) {
            int k0 = (t + 1) * 16;
            a0 = *(const float4*)(Ag + k0);
            b0 = *(const float4*)(Bg0 + (size_t)k0*1024);
            b1 = *(const float4*)(Bg1 + (size_t)k0*1024);
        }
#pragma unroll
        for (int k = 0; k < 16; k++) {
            float4 av  = *(const float4*)&sA[buf][k][ty*4];
            float4 bv0 = *(const float4*)&sB[buf][k][tx*4];
            float4 bv1 = *(const float4*)&sB[buf][k][64 + tx*4];
            float a4[4] = {av.x, av.y, av.z, av.w};
            float b8[8] = {bv0.x,bv0.y,bv0.z,bv0.w,bv1.x,bv1.y,bv1.z,bv1.w};
#pragma unroll
            for (int i = 0; i < 4; i++)
#pragma unroll
                for (int j = 0; j < 8; j++)
                    acc[i][j] = fmaf(a4[i], b8[j], acc[i][j]);
        }
        if (!last) {
            int nb = buf ^ 1;
            sA[nb][ak+0][ar]=a0.x; sA[nb][ak+1][ar]=a0.y; sA[nb][ak+2][ar]=a0.z; sA[nb][ak+3][ar]=a0.w;
            *(float4*)&sB[nb][bk  ][bc] = b0;
            *(float4*)&sB[nb][bk+8][bc] = b1;
            __syncthreads();
            buf = nb;
        }
    }
#pragma unroll
    for (int i = 0; i < 4; i++) {
        int row = bm + ty*4 + i;
        float4 v0; v0.x=acc[i][0]; v0.y=acc[i][1]; v0.z=acc[i][2]; v0.w=acc[i][3];
        float4 v1; v1.x=acc[i][4]; v1.y=acc[i][5]; v1.z=acc[i][6]; v1.w=acc[i][7];
        *(float4*)&g_PQ[(size_t)row*1024 + bn + tx*4]      = v0;
        *(float4*)&g_PQ[(size_t)row*1024 + bn + 64 + tx*4] = v1;
    }
}

// ====== entity chain, split-K: phase-1 kernels + deterministic reducers =====
__global__ void __launch_bounds__(128) k_l1p1(const float* __restrict__ hs,
                                              const float* __restrict__ w1) {
    __shared__ float st[E_*128];
    int b = blockIdx.z, kc = blockIdx.y << 7;
    int c = (blockIdx.x << 7) + threadIdx.x;
    for (int i = threadIdx.x; i < E_*128; i += 128) {
        int e = i >> 7, kk = i & 127;
        st[i] = hs[((size_t)(b*L_ + g_entpos[b*E_ + e]))*H_ + kc + kk];
    }
    __syncthreads();
    float acc[E_];
#pragma unroll
    for (int r = 0; r < E_; r++) acc[r] = 0.f;
    for (int kk = 0; kk < 128; kk++) {
        float w = w1[(size_t)(kc + kk)*DFF_ + c];
#pragma unroll
        for (int r = 0; r < E_; r++) acc[r] = fmaf(st[(r<<7) + kk], w, acc[r]);
    }
#pragma unroll
    for (int r = 0; r < E_; r++)
        g_part[((size_t)blockIdx.y*B_*E_ + b*E_ + r)*DFF_ + c] = acc[r];
}

__global__ void k_l1red(const float* __restrict__ b1) {
    int be = blockIdx.x;
    for (int c = threadIdx.x; c < DFF_; c += 128) {
        float s = b1[c];
#pragma unroll
        for (int kc = 0; kc < 6; kc++)
            s += g_part[((size_t)kc*B_*E_ + be)*DFF_ + c];
        g_h1[(size_t)be*DFF_ + c] = s > 0.f ? s : 0.01f*s;
    }
}

__global__ void __launch_bounds__(128) k_l2p1(const float* __restrict__ w2) {
    __shared__ float st[E_*128];
    int b = blockIdx.z, kc = blockIdx.y << 7;
    int c = (blockIdx.x << 7) + threadIdx.x;
    for (int i = threadIdx.x; i < E_*128; i += 128) {
        int e = i >> 7, kk = i & 127;
        st[i] = g_h1[((size_t)b*E_ + e)*DFF_ + kc + kk];
    }
    __syncthreads();
    float acc[E_];
#pragma unroll
    for (int r = 0; r < E_; r++) acc[r] = 0.f;
    for (int kk = 0; kk < 128; kk++) {
        float w = w2[(size_t)(kc + kk)*H_ + c];
#pragma unroll
        for (int r = 0; r < E_; r++) acc[r] = fmaf(st[(r<<7) + kk], w, acc[r]);
    }
#pragma unroll
    for (int r = 0; r < E_; r++)
        g_part[((size_t)blockIdx.y*B_*E_ + b*E_ + r)*H_ + c] = acc[r];
}

__global__ void k_l2red(const float* __restrict__ b2, const float* __restrict__ sb2) {
    __shared__ float red[256];
    int be = blockIdx.x;
    float dot = 0.f;
    for (int c = threadIdx.x; c < H_; c += 256) {
        float s = b2[c];
#pragma unroll
        for (int kc = 0; kc < 4; kc++)
            s += g_part[((size_t)kc*B_*E_ + be)*H_ + c];
        g_entvec[(size_t)be*H_ + c] = s;
        dot = fmaf(s, sb2[c], dot);
    }
    red[threadIdx.x] = dot;
    __syncthreads();
    if (threadIdx.x < 128) red[threadIdx.x] += red[threadIdx.x + 128];
    __syncthreads();
    if (threadIdx.x < 64) red[threadIdx.x] += red[threadIdx.x + 64];
    __syncthreads();
    if (threadIdx.x < 32) {
        float v = red[threadIdx.x] + red[threadIdx.x + 32];
#pragma unroll
        for (int o = 16; o; o >>= 1) v += __shfl_xor_sync(FULLM, v, o);
        if (threadIdx.x == 0) g_c[be] = v;
    }
}

__global__ void __launch_bounds__(128) k_gmp1() {
    __shared__ float st[E_*128];
    int b = blockIdx.z, kc = blockIdx.y << 7;
    int c = (blockIdx.x << 7) + threadIdx.x;
    for (int i = threadIdx.x; i < E_*128; i += 128) {
        int e = i >> 7, kk = i & 127;
        st[i] = g_entvec[((size_t)b*E_ + e)*H_ + kc + kk];
    }
    __syncthreads();
    float acc[E_];
#pragma unroll
    for (int r = 0; r < E_; r++) acc[r] = 0.f;
    for (int kk = 0; kk < 128; kk++) {
        float w = g_sw2t[(size_t)(kc + kk)*DFF_ + c];
#pragma unroll
        for (int r = 0; r < E_; r++) acc[r] = fmaf(st[(r<<7) + kk], w, acc[r]);
    }
#pragma unroll
    for (int r = 0; r < E_; r++)
        g_part[((size_t)blockIdx.y*B_*E_ + b*E_ + r)*DFF_ + c] = acc[r];
}

__global__ void k_gmred() {
    int be = blockIdx.x;
    for (int c = threadIdx.x; c < DFF_; c += 128) {
        float s = 0.f;
#pragma unroll
        for (int kc = 0; kc < 6; kc++)
            s += g_part[((size_t)kc*B_*E_ + be)*DFF_ + c];
        g_G[(size_t)be*DFF_ + c] = s;
    }
}

// --- logits (4-batch half): 2 spans/warp; per-span MAX 64-bit key -----------
__global__ void __launch_bounds__(256, 2) k_logits(const float* __restrict__ sb1,
                                                   float* __restrict__ out1,
                                                   float* __restrict__ sel, int b0) {
    if (sel) {   // zero this half's sel slice
        int gid = (blockIdx.y * gridDim.x + blockIdx.x) * 256 + threadIdx.x;
        int gstride = gridDim.x * gridDim.y * 256;
        for (int i = gid; i < 4*NE_; i += gstride) sel[(size_t)b0*NE_ + i] = 0.f;
    }
    __shared__ float sG[E_*DFF_];
    __shared__ float sb[DFF_];
    int b = b0 + blockIdx.y;
    for (int i = threadIdx.x; i < E_*DFF_; i += 256) sG[i] = g_G[(size_t)b*E_*DFF_ + i];
    for (int i = threadIdx.x; i < DFF_;    i += 256) sb[i] = sb1[i];
    __syncthreads();
    int warp = threadIdx.x >> 5, lane = threadIdx.x & 31;
    int n0 = blockIdx.x * 16 + warp * 2;
    if (n0 >= NSPAN) return;

    const float4* P4[2]; const float4* Q4[2]; int nn[2];
#pragma unroll
    for (int t = 0; t < 2; t++) {
        nn[t] = n0 + t;
        int n = nn[t] < NSPAN ? nn[t] : NSPAN - 1;
        int s, e; span_of(n, s, e);
        P4[t] = (const float4*)&g_PQ[(size_t)(b*W_ + s) * 1024];
        Q4[t] = (const float4*)&g_PQ[(size_t)(b*W_ + e) * 1024 + 512];
    }
    float acc[2][16];
#pragma unroll
    for (int t = 0; t < 2; t++)
#pragma unroll
        for (int e2 = 0; e2 < 16; e2++) acc[t][e2] = 0.f;

#pragma unroll
    for (int j = 0; j < 4; j++) {
        int kq = lane + j*32;
        float4 bb = ((const float4*)sb)[kq];
        float4 h[2];
#pragma unroll
        for (int t = 0; t < 2; t++) {
            float4 p = P4[t][kq], q = Q4[t][kq];
            float x0 = p.x+q.x+bb.x, x1 = p.y+q.y+bb.y;
            float x2 = p.z+q.z+bb.z, x3 = p.w+q.w+bb.w;
            h[t].x = x0 > 0.f ? x0 : 0.01f*x0;
            h[t].y = x1 > 0.f ? x1 : 0.01f*x1;
            h[t].z = x2 > 0.f ? x2 : 0.01f*x2;
            h[t].w = x3 > 0.f ? x3 : 0.01f*x3;
        }
#pragma unroll
        for (int e2 = 0; e2 < 16; e2++) {
            float4 g = ((const float4*)sG)[e2*128 + kq];
#pragma unroll
            for (int t = 0; t < 2; t++)
                acc[t][e2] = fmaf(h[t].x, g.x, fmaf(h[t].y, g.y,
                             fmaf(h[t].z, g.z, fmaf(h[t].w, g.w, acc[t][e2]))));
        }
    }
    int e2out = (lane >> 1) & 15;
#pragma unroll
    for (int t = 0; t < 2; t++) {
        float* v = acc[t];
#pragma unroll
        for (int d = 16; d > 1; d >>= 1) {
            int half = d >> 1;
#pragma unroll
            for (int i = 0; i < 8; i++) {
                if (i >= half) break;
                float give = (lane & d) ? v[i] : v[i + half];
                float got  = __shfl_xor_sync(FULLM, give, d);
                float keep = (lane & d) ? v[i + half] : v[i];
                v[i] = keep + got;
            }
        }
        v[0] += __shfl_xor_sync(FULLM, v[0], 1);
        bool valid = nn[t] < NSPAN;
        float lg = v[0] + g_c[b*E_ + e2out];
        if (!(lane & 1) && valid)
            out1[((size_t)b*NSPAN + nn[t])*E_ + e2out] = lg;
        float mv = (!(lane & 1)) ? lg : __int_as_float(0xff800000);
        int   mi = (!(lane & 1)) ? e2out : 9999;
#pragma unroll
        for (int o = 1; o < 32; o <<= 1) {
            float ov = __shfl_xor_sync(FULLM, mv, o);
            int   oi = __shfl_xor_sync(FULLM, mi, o);
            if (ov > mv || (ov == mv && oi < mi)) { mv = ov; mi = oi; }
        }
        if (lane == 0 && valid) {
            unsigned u = __float_as_uint(mv);
            unsigned asc = (u & 0x80000000u) ? ~u : (u | 0x80000000u);
            unsigned dsc = ~asc;
            unsigned idx = (unsigned)(nn[t]*E_ + mi);
            g_keys_in[(size_t)b*NSPAN + nn[t]] =
                ((unsigned long long)b << 49) | ((unsigned long long)dsc << 17) | idx;
        }
    }
}

// ------- greedy NMS decode (4-batch half): 1 block/batch --------------------
__global__ void __launch_bounds__(256) k_decode(float* __restrict__ sel, int b0) {
    int b = b0 + blockIdx.x;
    int tid = threadIdx.x, lane = tid & 31, warp = tid >> 5;
    __shared__ unsigned long long cov[8];
    __shared__ unsigned long long tile[512];
    __shared__ int done;
    if (tid < 8) cov[tid] = 0ULL;
    if (tid == 0) done = 0;
    __syncthreads();
    const unsigned long long* keys = g_keys_out + (size_t)b*NSPAN;
    for (int t0 = 0; t0 < NSPAN; t0 += 512) {
        int i0 = t0 + tid;
        tile[tid]       = (i0       < NSPAN) ? keys[i0]       : ~0ULL;
        tile[tid + 256] = (i0 + 256 < NSPAN) ? keys[i0 + 256] : ~0ULL;
        __syncthreads();
        if (warp == 0) {
            int stop = 0;
            for (int w0 = 0; w0 < 512; w0 += 32) {
                unsigned long long k = tile[w0 + lane];
                unsigned dsc = (unsigned)(k >> 17);
                unsigned asc = ~dsc;
                bool pos = asc > 0x80000000u;
                unsigned pb = __ballot_sync(FULLM, pos);
                if (pb == 0u) { stop = 1; break; }
                int idx = (int)(k & 0x1FFFFu);
                int n = idx >> 4;
                int s, e; span_of(n, s, e);
                int wd = s >> 6, off = s & 63, len = e - s + 1;
                unsigned long long bits = (1ULL << len) - 1ULL;
                unsigned long long m0 = bits << off;
                unsigned long long m1 = (off + len > 64) ? (bits >> (64 - off)) : 0ULL;
                unsigned long long c0 = cov[wd];
                unsigned long long c1 = (wd + 1 < 8) ? cov[wd+1] : 0ULL;
                bool alive = pos && !((c0 & m0) | (c1 & m1));
                unsigned ball = __ballot_sync(FULLM, alive);
                while (ball) {
                    int leader = __ffs(ball) - 1;
                    int lw = __shfl_sync(FULLM, wd, leader);
                    unsigned long long lm0 = __shfl_sync(FULLM, m0, leader);
                    unsigned long long lm1 = __shfl_sync(FULLM, m1, leader);
                    int lidx = __shfl_sync(FULLM, idx, leader);
                    if (lane == leader) {
                        cov[lw] |= lm0;
                        if (lw + 1 < 8) cov[lw+1] |= lm1;
                        sel[(size_t)b*NE_ + lidx] = 1.0f;
                        alive = false;
                    } else if (alive && lane > leader) {
                        unsigned long long o = 0ULL;
                        if      (lw == wd)     o = (lm0 & m0) | (lm1 & m1);
                        else if (lw == wd - 1) o = lm1 & m0;
                        else if (lw == wd + 1) o = lm0 & m1;
                        if (o) alive = false;
                    }
                    ball = __ballot_sync(FULLM, alive);
                }
                __syncwarp();
                unsigned long long cw = (lane < 8) ? cov[lane] : 0ULL;
                int pc = __popcll(cw);
#pragma unroll
                for (int o = 16; o; o >>= 1) pc += __shfl_xor_sync(FULLM, pc, o);
                if (pc >= W_) { stop = 1; break; }
                if (pb != FULLM) { stop = 1; break; }
            }
            if (lane == 0 && stop) done = 1;
        }
        __syncthreads();
        if (done) break;
        __syncthreads();
    }
}

extern "C" void kernel_launch(void* const* d_in, const int* in_sizes, int n_in,
                              void* d_out, int out_size) {
    const float* hs   = (const float*)d_in[0];
    const float* ew1  = (const float*)d_in[1];
    const float* eb1  = (const float*)d_in[2];
    const float* ew2  = (const float*)d_in[3];
    const float* eb2  = (const float*)d_in[4];
    const float* sw1  = (const float*)d_in[5];
    const float* sb1  = (const float*)d_in[6];
    const float* sw2  = (const float*)d_in[7];
    const float* sb2  = (const float*)d_in[8];
    const int* tmask  = (const int*)d_in[9];
    const int* emask  = (const int*)d_in[10];
    const int* widx   = (const int*)d_in[11];
    float* out = (float*)d_out;
    int write_sel = (out_size >= 2*BNE_);
    float* sel = write_sel ? out + BNE_ : nullptr;

    // ONE extra stream + events (proven allocation-safe in R11)
    cudaStream_t sB;
    cudaStreamCreateWithFlags(&sB, cudaStreamNonBlocking);
    cudaEvent_t e0, eA, eP, eC, eG, eT;
    cudaEventCreateWithFlags(&e0, cudaEventDisableTiming);
    cudaEventCreateWithFlags(&eA, cudaEventDisableTiming);
    cudaEventCreateWithFlags(&eP, cudaEventDisableTiming);
    cudaEventCreateWithFlags(&eC, cudaEventDisableTiming);
    cudaEventCreateWithFlags(&eG, cudaEventDisableTiming);
    cudaEventCreateWithFlags(&eT, cudaEventDisableTiming);

    void *pin, *pout, *ptmp;
    cudaGetSymbolAddress(&pin,  g_keys_in);
    cudaGetSymbolAddress(&pout, g_keys_out);
    cudaGetSymbolAddress(&ptmp, g_cub_temp);
    size_t half_tmp = sizeof(g_cub_temp) / 2;

    // stream 0: setup0 -> build -> pool2 -> gemm
    k_setup0<<<64, 256>>>(emask);
    cudaEventRecord(e0, 0);
    cudaEventRecord(eA, 0);
    k_build<<<(B_*L_ + 255)/256, 256>>>(tmask, widx);

    // stream B: prep -> entity chain
    cudaStreamWaitEvent(sB, e0, 0);
    k_prep<<<512, 256, 0, sB>>>(sw1, sw2);
    cudaEventRecord(eP, sB);
    k_pool2<<<(B_*W_ + 7)/8, 256>>>(hs);               // stream 0, slot 3 (ncu)
    cudaStreamWaitEvent(sB, eA, 0);
    k_l1p1<<<dim3(4, 6, B_), 128, 0, sB>>>(hs, ew1);
    k_l1red<<<B_*E_, 128, 0, sB>>>(eb1);
    k_l2p1<<<dim3(6, 4, B_), 128, 0, sB>>>(ew2);
    k_l2red<<<B_*E_, 256, 0, sB>>>(eb2, sb2);
    k_gmp1<<<dim3(4, 6, B_), 128, 0, sB>>>();
    k_gmred<<<B_*E_, 128, 0, sB>>>();
    cudaEventRecord(eC, sB);

    // stream 0: gemm (needs Bpack)
    cudaStreamWaitEvent(0, eP, 0);
    k_gemm<<<dim3(8, 63), 256>>>();
    cudaEventRecord(eG, 0);

    // --- split tail: stream 0 handles batches 0-3, stream B handles 4-7 ----
    dim3 lgrid((NSPAN + 15)/16, 4);
    // stream 0 half
    cudaStreamWaitEvent(0, eC, 0);
    k_logits<<<lgrid, 256>>>(sb1, out, sel, 0);
    // stream B half (chain already on sB; needs gemm)
    cudaStreamWaitEvent(sB, eG, 0);
    k_logits<<<lgrid, 256, 0, sB>>>(sb1, out, sel, 4);

    if (write_sel) {
        size_t tb = 0;
        cub::DeviceRadixSort::SortKeys(nullptr, tb,
            (const unsigned long long*)pin, (unsigned long long*)pout, HNS_, 17, 52);
        if (tb <= half_tmp) {
            cub::DeviceRadixSort::SortKeys(ptmp, tb,
                (const unsigned long long*)pin, (unsigned long long*)pout,
                HNS_, 17, 52, 0);
            cub::DeviceRadixSort::SortKeys((unsigned char*)ptmp + half_tmp, tb,
                (const unsigned long long*)pin + HNS_, (unsigned long long*)pout + HNS_,
                HNS_, 17, 52, sB);
        }
        k_decode<<<4, 256>>>(sel, 0);
        k_decode<<<4, 256, 0, sB>>>(sel, 4);
    }
    cudaEventRecord(eT, sB);
    cudaStreamWaitEvent(0, eT, 0);
}

// round 15
// speedup vs baseline: 1.1126x; 1.0466x over previous
#include <cuda_runtime.h>
#include <cub/cub.cuh>
#include <cstdint>

#define B_    8
#define L_    1024
#define H_    768
#define E_    16
#define W_    504
#define DFF_  512
#define NSPAN 5982
#define NE_   (NSPAN*E_)        /* 95712 */
#define BNE_  (B_*NE_)          /* 765696 */
#define BNS_  (B_*NSPAN)        /* 47856 */
#define HNS_  (4*NSPAN)         /* half: 23928 */
#define FULLM 0xffffffffu

// ---------------- scratch (device globals; no runtime allocation) ----------
__device__ float g_word_emb[B_*W_*H_];
__device__ int   g_cnt[B_*W_];
__device__ int   g_wlist[B_*W_*8];
__device__ int   g_entpos[B_*E_];
__device__ float g_h1[B_*E_*DFF_];
__device__ float g_entvec[B_*E_*H_];
__device__ float g_G[B_*E_*DFF_];               // span_w2 @ ent_vec^T
__device__ float g_c[B_*E_];                    // span_b2 . ent_vec
__device__ float g_Bpack[H_*2*DFF_];            // [768,1024] packed span_w1
__device__ float g_sw2t[H_*DFF_];               // span_w2 transposed [768,512]
__device__ float g_part[6*B_*E_*DFF_];          // split-K partials (reused 3x)
__device__ float g_PQ[B_*W_*2*DFF_];            // per word: P(512) | Q(512)
__device__ unsigned long long g_keys_in[BNS_];
__device__ unsigned long long g_keys_out[BNS_];
__device__ __align__(256) unsigned char g_cub_temp[16u*1024u*1024u]; // 2 x 8MB

// span id -> (start, end), pure arithmetic
__device__ __forceinline__ void span_of(int n, int& s, int& e) {
    if (n < 5916) { s = n / 12; e = s + n % 12; }
    else {
        int r = n - 5916; s = 493;
        while (r >= W_ - s) { r -= W_ - s; s++; }
        e = s + r;
    }
}

// -------- setup0: zero counters + entity-position scan (stream 0) -----------
__global__ void k_setup0(const int* __restrict__ emask) {
    int i = blockIdx.x * blockDim.x + threadIdx.x;
    int stride = gridDim.x * blockDim.x;
    for (int t = i; t < B_*W_; t += stride) g_cnt[t] = 0;
    if (blockIdx.x == 0 && threadIdx.x < 256) {
        int warp = threadIdx.x >> 5, lane = threadIdx.x & 31;
        int b = warp, cnt = 0;
        for (int pass = 0; pass < 2 && cnt < E_; pass++) {
            for (int base = 0; base < L_ && cnt < E_; base += 32) {
                int m = emask[b*L_ + base + lane];
                unsigned bal = __ballot_sync(FULLM, pass == 0 ? (m == 1) : (m != 1));
                while (bal && cnt < E_) {
                    int j = __ffs(bal) - 1; bal &= bal - 1;
                    if (lane == 0) g_entpos[b*E_ + cnt] = base + j;
                    cnt++;
                }
            }
        }
    }
}

// -------- prep: pack span_w1 + transpose span_w2 (stream B) -----------------
__global__ void k_prep(const float* __restrict__ sw1, const float* __restrict__ sw2) {
    int i = blockIdx.x * blockDim.x + threadIdx.x;
    int stride = gridDim.x * blockDim.x;
    for (int t = i; t < H_*2*DFF_; t += stride) {
        int k = t >> 10, j = t & 1023;
        g_Bpack[t] = (j < DFF_) ? sw1[(size_t)k*DFF_ + j]
                                : sw1[(size_t)(H_ + k)*DFF_ + (j - DFF_)];
    }
    for (int t = i; t < H_*DFF_; t += stride) {
        int h = t / DFF_, c = t - h*DFF_;
        g_sw2t[t] = sw2[(size_t)c*H_ + h];
    }
}

// ---------------- build per-word token lists --------------------------------
__global__ void k_build(const int* __restrict__ tmask, const int* __restrict__ widx) {
    int t = blockIdx.x * blockDim.x + threadIdx.x;
    if (t >= B_*L_) return;
    if (tmask[t] != 1) return;
    int w = widx[t];
    if (w < 0 || w >= W_) return;
    int b = t >> 10;
    int slot = atomicAdd(&g_cnt[b*W_ + w], 1);
    if (slot < 8) g_wlist[(b*W_ + w)*8 + slot] = t;
}

// ---------------- gather mean pooling: 1 warp per word ----------------------
__global__ void __launch_bounds__(256) k_pool2(const float* __restrict__ hs) {
    int word = blockIdx.x * 8 + (threadIdx.x >> 5);
    if (word >= B_*W_) return;
    int lane = threadIdx.x & 31;
    int cnt = g_cnt[word];
    int m = cnt < 8 ? cnt : 8;
    int tk[8];
#pragma unroll
    for (int i = 0; i < 8; i++) tk[i] = (i < m) ? g_wlist[word*8 + i] : 0x7fffffff;
#pragma unroll
    for (int p = 0; p < 8; p++)
#pragma unroll
        for (int i = 0; i < 7; i++)
            if (tk[i] > tk[i+1]) { int z = tk[i]; tk[i] = tk[i+1]; tk[i+1] = z; }
    float ax[6], ay[6], az[6], aw[6];
#pragma unroll
    for (int c = 0; c < 6; c++) { ax[c]=0.f; ay[c]=0.f; az[c]=0.f; aw[c]=0.f; }
#pragma unroll
    for (int j = 0; j < 8; j++) {
        if (tk[j] == 0x7fffffff) continue;
        const float4* src = (const float4*)&hs[(size_t)tk[j]*H_];
#pragma unroll
        for (int c = 0; c < 6; c++) {
            float4 v = src[lane + c*32];
            ax[c]+=v.x; ay[c]+=v.y; az[c]+=v.z; aw[c]+=v.w;
        }
    }
    float inv = 1.f / (float)(cnt > 1 ? cnt : 1);
    float4* dst = (float4*)&g_word_emb[(size_t)word*H_];
#pragma unroll
    for (int c = 0; c < 6; c++) {
        float4 v; v.x=ax[c]*inv; v.y=ay[c]*inv; v.z=az[c]*inv; v.w=aw[c]*inv;
        dst[lane + c*32] = v;
    }
}

// -------- GEMM (M-tile slice): PQ rows [y0*64, (y0+ny)*64) ------------------
__global__ void __launch_bounds__(256) k_gemm(int y0) {
    __shared__ float sA[2][16][68];
    __shared__ float sB[2][16][128];
    int bm = (blockIdx.y + y0) * 64, bn = blockIdx.x * 128;
    int tid = threadIdx.x;
    int tx = tid & 15, ty = tid >> 4;
    int ar = tid >> 2, ak = (tid & 3) * 4;
    int bk = tid >> 5, bc = (tid & 31) * 4;
    const float* Ag  = &g_word_emb[(size_t)(bm + ar)*H_ + ak];
    const float* Bg0 = &g_Bpack[(size_t)bk*1024 + bn + bc];
    const float* Bg1 = &g_Bpack[(size_t)(bk+8)*1024 + bn + bc];

    float acc[4][8];
#pragma unroll
    for (int i = 0; i < 4; i++)
#pragma unroll
        for (int j = 0; j < 8; j++) acc[i][j] = 0.f;

    float4 a0 = *(const float4*)(Ag);
    float4 b0 = *(const float4*)(Bg0);
    float4 b1 = *(const float4*)(Bg1);
    int buf = 0;
    sA[0][ak+0][ar]=a0.x; sA[0][ak+1][ar]=a0.y; sA[0][ak+2][ar]=a0.z; sA[0][ak+3][ar]=a0.w;
    *(float4*)&sB[0][bk  ][bc] = b0;
    *(float4*)&sB[0][bk+8][bc] = b1;
    __syncthreads();

    for (int t = 0; t < 48; t++) {
        bool last = (t == 47);
        if (!last) {
            int k0 = (t + 1) * 16;
            a0 = *(const float4*)(Ag + k0);
            b0 = *(const float4*)(Bg0 + (size_t)k0*1024);
            b1 = *(const float4*)(Bg1 + (size_t)k0*1024);
        }
#pragma unroll
        for (int k = 0; k < 16; k++) {
            float4 av  = *(const float4*)&sA[buf][k][ty*4];
            float4 bv0 = *(const float4*)&sB[buf][k][tx*4];
            float4 bv1 = *(const float4*)&sB[buf][k][64 + tx*4];
            float a4[4] = {av.x, av.y, av.z, av.w};
            float b8[8] = {bv0.x,bv0.y,bv0.z,bv0.w,bv1.x,bv1.y,bv1.z,bv1.w};
#pragma unroll
            for (int i = 0; i < 4; i++)
#pragma unroll
                for (int j = 0; j < 8; j++)
                    acc[i][j] = fmaf(a4[i], b8[j], acc[i][j]);
        }
        if (!last) {
            int nb = buf ^ 1;
            sA[nb][ak+0][ar]=a0.x; sA[nb][ak+1][ar]=a0.y; sA[nb][ak+2][ar]=a0.z; sA[nb][ak+3][ar]=a0.w;
            *(float4*)&sB[nb][bk  ][bc] = b0;
            *(float4*)&sB[nb][bk+8][bc] = b1;
            __syncthreads();
            buf = nb;
        }
    }
#pragma unroll
    for (int i = 0; i < 4; i++) {
        int row = bm + ty*4 + i;
        float4 v0; v0.x=acc[i][0]; v0.y=acc[i][1]; v0.z=acc[i][2]; v0.w=acc[i][3];
        float4 v1; v1.x=acc[i][4]; v1.y=acc[i][5]; v1.z=acc[i][6]; v1.w=acc[i][7];
        *(float4*)&g_PQ[(size_t)row*1024 + bn + tx*4]      = v0;
        *(float4*)&g_PQ[(size_t)row*1024 + bn + 64 + tx*4] = v1;
    }
}

// ====== entity chain, split-K: phase-1 kernels + deterministic reducers =====
__global__ void __launch_bounds__(128) k_l1p1(const float* __restrict__ hs,
                                              const float* __restrict__ w1) {
    __shared__ float st[E_*128];
    int b = blockIdx.z, kc = blockIdx.y << 7;
    int c = (blockIdx.x << 7) + threadIdx.x;
    for (int i = threadIdx.x; i < E_*128; i += 128) {
        int e = i >> 7, kk = i & 127;
        st[i] = hs[((size_t)(b*L_ + g_entpos[b*E_ + e]))*H_ + kc + kk];
    }
    __syncthreads();
    float acc[E_];
#pragma unroll
    for (int r = 0; r < E_; r++) acc[r] = 0.f;
    for (int kk = 0; kk < 128; kk++) {
        float w = w1[(size_t)(kc + kk)*DFF_ + c];
#pragma unroll
        for (int r = 0; r < E_; r++) acc[r] = fmaf(st[(r<<7) + kk], w, acc[r]);
    }
#pragma unroll
    for (int r = 0; r < E_; r++)
        g_part[((size_t)blockIdx.y*B_*E_ + b*E_ + r)*DFF_ + c] = acc[r];
}

__global__ void k_l1red(const float* __restrict__ b1) {
    int be = blockIdx.x;
    for (int c = threadIdx.x; c < DFF_; c += 128) {
        float s = b1[c];
#pragma unroll
        for (int kc = 0; kc < 6; kc++)
            s += g_part[((size_t)kc*B_*E_ + be)*DFF_ + c];
        g_h1[(size_t)be*DFF_ + c] = s > 0.f ? s : 0.01f*s;
    }
}

__global__ void __launch_bounds__(128) k_l2p1(const float* __restrict__ w2) {
    __shared__ float st[E_*128];
    int b = blockIdx.z, kc = blockIdx.y << 7;
    int c = (blockIdx.x << 7) + threadIdx.x;
    for (int i = threadIdx.x; i < E_*128; i += 128) {
        int e = i >> 7, kk = i & 127;
        st[i] = g_h1[((size_t)b*E_ + e)*DFF_ + kc + kk];
    }
    __syncthreads();
    float acc[E_];
#pragma unroll
    for (int r = 0; r < E_; r++) acc[r] = 0.f;
    for (int kk = 0; kk < 128; kk++) {
        float w = w2[(size_t)(kc + kk)*H_ + c];
#pragma unroll
        for (int r = 0; r < E_; r++) acc[r] = fmaf(st[(r<<7) + kk], w, acc[r]);
    }
#pragma unroll
    for (int r = 0; r < E_; r++)
        g_part[((size_t)blockIdx.y*B_*E_ + b*E_ + r)*H_ + c] = acc[r];
}

__global__ void k_l2red(const float* __restrict__ b2, const float* __restrict__ sb2) {
    __shared__ float red[256];
    int be = blockIdx.x;
    float dot = 0.f;
    for (int c = threadIdx.x; c < H_; c += 256) {
        float s = b2[c];
#pragma unroll
        for (int kc = 0; kc < 4; kc++)
            s += g_part[((size_t)kc*B_*E_ + be)*H_ + c];
        g_entvec[(size_t)be*H_ + c] = s;
        dot = fmaf(s, sb2[c], dot);
    }
    red[threadIdx.x] = dot;
    __syncthreads();
    if (threadIdx.x < 128) red[threadIdx.x] += red[threadIdx.x + 128];
    __syncthreads();
    if (threadIdx.x < 64) red[threadIdx.x] += red[threadIdx.x + 64];
    __syncthreads();
    if (threadIdx.x < 32) {
        float v = red[threadIdx.x] + red[threadIdx.x + 32];
#pragma unroll
        for (int o = 16; o; o >>= 1) v += __shfl_xor_sync(FULLM, v, o);
        if (threadIdx.x == 0) g_c[be] = v;
    }
}

__global__ void __launch_bounds__(128) k_gmp1() {
    __shared__ float st[E_*128];
    int b = blockIdx.z, kc = blockIdx.y << 7;
    int c = (blockIdx.x << 7) + threadIdx.x;
    for (int i = threadIdx.x; i < E_*128; i += 128) {
        int e = i >> 7, kk = i & 127;
        st[i] = g_entvec[((size_t)b*E_ + e)*H_ + kc + kk];
    }
    __syncthreads();
    float acc[E_];
#pragma unroll
    for (int r = 0; r < E_; r++) acc[r] = 0.f;
    for (int kk = 0; kk < 128; kk++) {
        float w = g_sw2t[(size_t)(kc + kk)*DFF_ + c];
#pragma unroll
        for (int r = 0; r < E_; r++) acc[r] = fmaf(st[(r<<7) + kk], w, acc[r]);
    }
#pragma unroll
    for (int r = 0; r < E_; r++)
        g_part[((size_t)blockIdx.y*B_*E_ + b*E_ + r)*DFF_ + c] = acc[r];
}

__global__ void k_gmred() {
    int be = blockIdx.x;
    for (int c = threadIdx.x; c < DFF_; c += 128) {
        float s = 0.f;
#pragma unroll
        for (int kc = 0; kc < 6; kc++)
            s += g_part[((size_t)kc*B_*E_ + be)*DFF_ + c];
        g_G[(size_t)be*DFF_ + c] = s;
    }
}

// --- logits (4-batch half): 2 spans/warp; per-span MAX 64-bit key -----------
__global__ void __launch_bounds__(256, 2) k_logits(const float* __restrict__ sb1,
                                                   float* __restrict__ out1,
                                                   float* __restrict__ sel, int b0) {
    if (sel) {   // zero this half's sel slice
        int gid = (blockIdx.y * gridDim.x + blockIdx.x) * 256 + threadIdx.x;
        int gstride = gridDim.x * gridDim.y * 256;
        for (int i = gid; i < 4*NE_; i += gstride) sel[(size_t)b0*NE_ + i] = 0.f;
    }
    __shared__ float sG[E_*DFF_];
    __shared__ float sb[DFF_];
    int b = b0 + blockIdx.y;
    for (int i = threadIdx.x; i < E_*DFF_; i += 256) sG[i] = g_G[(size_t)b*E_*DFF_ + i];
    for (int i = threadIdx.x; i < DFF_;    i += 256) sb[i] = sb1[i];
    __syncthreads();
    int warp = threadIdx.x >> 5, lane = threadIdx.x & 31;
    int n0 = blockIdx.x * 16 + warp * 2;
    if (n0 >= NSPAN) return;

    const float4* P4[2]; const float4* Q4[2]; int nn[2];
#pragma unroll
    for (int t = 0; t < 2; t++) {
        nn[t] = n0 + t;
        int n = nn[t] < NSPAN ? nn[t] : NSPAN - 1;
        int s, e; span_of(n, s, e);
        P4[t] = (const float4*)&g_PQ[(size_t)(b*W_ + s) * 1024];
        Q4[t] = (const float4*)&g_PQ[(size_t)(b*W_ + e) * 1024 + 512];
    }
    float acc[2][16];
#pragma unroll
    for (int t = 0; t < 2; t++)
#pragma unroll
        for (int e2 = 0; e2 < 16; e2++) acc[t][e2] = 0.f;

#pragma unroll
    for (int j = 0; j < 4; j++) {
        int kq = lane + j*32;
        float4 bb = ((const float4*)sb)[kq];
        float4 h[2];
#pragma unroll
        for (int t = 0; t < 2; t++) {
            float4 p = P4[t][kq], q = Q4[t][kq];
            float x0 = p.x+q.x+bb.x, x1 = p.y+q.y+bb.y;
            float x2 = p.z+q.z+bb.z, x3 = p.w+q.w+bb.w;
            h[t].x = x0 > 0.f ? x0 : 0.01f*x0;
            h[t].y = x1 > 0.f ? x1 : 0.01f*x1;
            h[t].z = x2 > 0.f ? x2 : 0.01f*x2;
            h[t].w = x3 > 0.f ? x3 : 0.01f*x3;
        }
#pragma unroll
        for (int e2 = 0; e2 < 16; e2++) {
            float4 g = ((const float4*)sG)[e2*128 + kq];
#pragma unroll
            for (int t = 0; t < 2; t++)
                acc[t][e2] = fmaf(h[t].x, g.x, fmaf(h[t].y, g.y,
                             fmaf(h[t].z, g.z, fmaf(h[t].w, g.w, acc[t][e2]))));
        }
    }
    int e2out = (lane >> 1) & 15;
#pragma unroll
    for (int t = 0; t < 2; t++) {
        float* v = acc[t];
#pragma unroll
        for (int d = 16; d > 1; d >>= 1) {
            int half = d >> 1;
#pragma unroll
            for (int i = 0; i < 8; i++) {
                if (i >= half) break;
                float give = (lane & d) ? v[i] : v[i + half];
                float got  = __shfl_xor_sync(FULLM, give, d);
                float keep = (lane & d) ? v[i + half] : v[i];
                v[i] = keep + got;
            }
        }
        v[0] += __shfl_xor_sync(FULLM, v[0], 1);
        bool valid = nn[t] < NSPAN;
        float lg = v[0] + g_c[b*E_ + e2out];
        if (!(lane & 1) && valid)
            out1[((size_t)b*NSPAN + nn[t])*E_ + e2out] = lg;
        float mv = (!(lane & 1)) ? lg : __int_as_float(0xff800000);
        int   mi = (!(lane & 1)) ? e2out : 9999;
#pragma unroll
        for (int o = 1; o < 32; o <<= 1) {
            float ov = __shfl_xor_sync(FULLM, mv, o);
            int   oi = __shfl_xor_sync(FULLM, mi, o);
            if (ov > mv || (ov == mv && oi < mi)) { mv = ov; mi = oi; }
        }
        if (lane == 0 && valid) {
            unsigned u = __float_as_uint(mv);
            unsigned asc = (u & 0x80000000u) ? ~u : (u | 0x80000000u);
            unsigned dsc = ~asc;
            unsigned idx = (unsigned)(nn[t]*E_ + mi);
            g_keys_in[(size_t)b*NSPAN + nn[t]] =
                ((unsigned long long)b << 49) | ((unsigned long long)dsc << 17) | idx;
        }
    }
}

// ------- greedy NMS decode (4-batch half): 1 block/batch --------------------
__global__ void __launch_bounds__(256) k_decode(float* __restrict__ sel, int b0) {
    int b = b0 + blockIdx.x;
    int tid = threadIdx.x, lane = tid & 31, warp = tid >> 5;
    __shared__ unsigned long long cov[8];
    __shared__ unsigned long long tile[512];
    __shared__ int done;
    if (tid < 8) cov[tid] = 0ULL;
    if (tid == 0) done = 0;
    __syncthreads();
    const unsigned long long* keys = g_keys_out + (size_t)b*NSPAN;
    for (int t0 = 0; t0 < NSPAN; t0 += 512) {
        int i0 = t0 + tid;
        tile[tid]       = (i0       < NSPAN) ? keys[i0]       : ~0ULL;
        tile[tid + 256] = (i0 + 256 < NSPAN) ? keys[i0 + 256] : ~0ULL;
        __syncthreads();
        if (warp == 0) {
            int stop = 0;
            for (int w0 = 0; w0 < 512; w0 += 32) {
                unsigned long long k = tile[w0 + lane];
                unsigned dsc = (unsigned)(k >> 17);
                unsigned asc = ~dsc;
                bool pos = asc > 0x80000000u;
                unsigned pb = __ballot_sync(FULLM, pos);
                if (pb == 0u) { stop = 1; break; }
                int idx = (int)(k & 0x1FFFFu);
                int n = idx >> 4;
                int s, e; span_of(n, s, e);
                int wd = s >> 6, off = s & 63, len = e - s + 1;
                unsigned long long bits = (1ULL << len) - 1ULL;
                unsigned long long m0 = bits << off;
                unsigned long long m1 = (off + len > 64) ? (bits >> (64 - off)) : 0ULL;
                unsigned long long c0 = cov[wd];
                unsigned long long c1 = (wd + 1 < 8) ? cov[wd+1] : 0ULL;
                bool alive = pos && !((c0 & m0) | (c1 & m1));
                unsigned ball = __ballot_sync(FULLM, alive);
                while (ball) {
                    int leader = __ffs(ball) - 1;
                    int lw = __shfl_sync(FULLM, wd, leader);
                    unsigned long long lm0 = __shfl_sync(FULLM, m0, leader);
                    unsigned long long lm1 = __shfl_sync(FULLM, m1, leader);
                    int lidx = __shfl_sync(FULLM, idx, leader);
                    if (lane == leader) {
                        cov[lw] |= lm0;
                        if (lw + 1 < 8) cov[lw+1] |= lm1;
                        sel[(size_t)b*NE_ + lidx] = 1.0f;
                        alive = false;
                    } else if (alive && lane > leader) {
                        unsigned long long o = 0ULL;
                        if      (lw == wd)     o = (lm0 & m0) | (lm1 & m1);
                        else if (lw == wd - 1) o = lm1 & m0;
                        else if (lw == wd + 1) o = lm0 & m1;
                        if (o) alive = false;
                    }
                    ball = __ballot_sync(FULLM, alive);
                }
                __syncwarp();
                unsigned long long cw = (lane < 8) ? cov[lane] : 0ULL;
                int pc = __popcll(cw);
#pragma unroll
                for (int o = 16; o; o >>= 1) pc += __shfl_xor_sync(FULLM, pc, o);
                if (pc >= W_) { stop = 1; break; }
                if (pb != FULLM) { stop = 1; break; }
            }
            if (lane == 0 && stop) done = 1;
        }
        __syncthreads();
        if (done) break;
        __syncthreads();
    }
}

extern "C" void kernel_launch(void* const* d_in, const int* in_sizes, int n_in,
                              void* d_out, int out_size) {
    const float* hs   = (const float*)d_in[0];
    const float* ew1  = (const float*)d_in[1];
    const float* eb1  = (const float*)d_in[2];
    const float* ew2  = (const float*)d_in[3];
    const float* eb2  = (const float*)d_in[4];
    const float* sw1  = (const float*)d_in[5];
    const float* sb1  = (const float*)d_in[6];
    const float* sw2  = (const float*)d_in[7];
    const float* sb2  = (const float*)d_in[8];
    const int* tmask  = (const int*)d_in[9];
    const int* emask  = (const int*)d_in[10];
    const int* widx   = (const int*)d_in[11];
    float* out = (float*)d_out;
    int write_sel = (out_size >= 2*BNE_);
    float* sel = write_sel ? out + BNE_ : nullptr;

    // ONE extra stream + events (proven allocation-safe)
    cudaStream_t sB;
    cudaStreamCreateWithFlags(&sB, cudaStreamNonBlocking);
    cudaEvent_t e0, eA, eP, eC, eG1, eT;
    cudaEventCreateWithFlags(&e0, cudaEventDisableTiming);
    cudaEventCreateWithFlags(&eA, cudaEventDisableTiming);
    cudaEventCreateWithFlags(&eP, cudaEventDisableTiming);
    cudaEventCreateWithFlags(&eC, cudaEventDisableTiming);
    cudaEventCreateWithFlags(&eG1, cudaEventDisableTiming);
    cudaEventCreateWithFlags(&eT, cudaEventDisableTiming);

    void *pin, *pout, *ptmp;
    cudaGetSymbolAddress(&pin,  g_keys_in);
    cudaGetSymbolAddress(&pout, g_keys_out);
    cudaGetSymbolAddress(&ptmp, g_cub_temp);
    size_t half_tmp = sizeof(g_cub_temp) / 2;

    // stream 0: setup0 -> build -> pool2 -> gemmP1 -> gemmP2
    k_setup0<<<64, 256>>>(emask);
    cudaEventRecord(e0, 0);
    cudaEventRecord(eA, 0);
    k_build<<<(B_*L_ + 255)/256, 256>>>(tmask, widx);

    // stream B: prep -> entity chain
    cudaStreamWaitEvent(sB, e0, 0);
    k_prep<<<512, 256, 0, sB>>>(sw1, sw2);
    cudaEventRecord(eP, sB);
    k_pool2<<<(B_*W_ + 7)/8, 256>>>(hs);               // stream 0, slot 3 (ncu)
    cudaStreamWaitEvent(sB, eA, 0);
    k_l1p1<<<dim3(4, 6, B_), 128, 0, sB>>>(hs, ew1);
    k_l1red<<<B_*E_, 128, 0, sB>>>(eb1);
    k_l2p1<<<dim3(6, 4, B_), 128, 0, sB>>>(ew2);
    k_l2red<<<B_*E_, 256, 0, sB>>>(eb2, sb2);
    k_gmp1<<<dim3(4, 6, B_), 128, 0, sB>>>();
    k_gmred<<<B_*E_, 128, 0, sB>>>();
    cudaEventRecord(eC, sB);

    // stream 0: gemm part1 (tiles 0..31 -> rows 0..2047 covers batches 0-3)
    cudaStreamWaitEvent(0, eP, 0);
    k_gemm<<<dim3(8, 32), 256>>>(0);
    cudaEventRecord(eG1, 0);
    // gemm part2 (tiles 32..62 -> rows 2048..4031)
    k_gemm<<<dim3(8, 31), 256>>>(32);

    dim3 lgrid((NSPAN + 15)/16, 4);
    size_t tb = 0;
    cub::DeviceRadixSort::SortKeys(nullptr, tb,
        (const unsigned long long*)pin, (unsigned long long*)pout, HNS_, 17, 52);
    bool fits = (tb <= half_tmp);

    // stream B half-tail (batches 0-3): overlaps gemm part2 on stream 0
    cudaStreamWaitEvent(sB, eG1, 0);   // chain already in-order on sB
    k_logits<<<lgrid, 256, 0, sB>>>(sb1, out, sel, 0);
    if (write_sel && fits) {
        cub::DeviceRadixSort::SortKeys(ptmp, tb,
            (const unsigned long long*)pin, (unsigned long long*)pout,
            HNS_, 17, 52, sB);
        k_decode<<<4, 256, 0, sB>>>(sel, 0);
    }
    cudaEventRecord(eT, sB);

    // stream 0 half-tail (batches 4-7): after full gemm + chain
    cudaStreamWaitEvent(0, eC, 0);
    k_logits<<<lgrid, 256>>>(sb1, out, sel, 4);
    if (write_sel && fits) {
        cub::DeviceRadixSort::SortKeys((unsigned char*)ptmp + half_tmp, tb,
            (const unsigned long long*)pin + HNS_, (unsigned long long*)pout + HNS_,
            HNS_, 17, 52, 0);
        k_decode<<<4, 256>>>(sel, 4);
    }
    cudaStreamWaitEvent(0, eT, 0);
}